// round 14
// baseline (speedup 1.0000x reference)
#include <cuda_runtime.h>
#include <cuda_fp16.h>
#include <math.h>
#include <stdint.h>

#define BSZ   8
#define HD    128
#define LSEQ  8192
#define PD    256
#define NC2   16
#define CL    (LSEQ / NC2)   // 512
#define SENT  0x7FC00001u    // NaN-payload sentinel ("not published")

// ---------------- scratch ----------------
__device__ __align__(16) __half g_brh[(size_t)BSZ * PD * LSEQ];  // Bu real (planar b,p,l) fp16
__device__ __align__(16) __half g_bih[(size_t)BSZ * PD * LSEQ];  // Bu imag
__device__ __align__(16) __half g_xr[(size_t)BSZ * PD * LSEQ];   // x real (fp16)
__device__ __align__(16) __half g_xi[(size_t)BSZ * PD * LSEQ];   // x imag (fp16)
__device__ __align__(8) unsigned long long g_S[BSZ * NC2 * PD];  // packed chunk-end states
// Packed per-lane mma A-fragments (fp16): [m16blk][ks][lane]
__device__ __align__(16) uint4 g_WbPk[32 * 8 * 32];    // Wb: M=512, K=128
__device__ __align__(16) uint4 g_WcPk[8 * 40 * 32];    // Wc: M=128, K=640

__device__ __forceinline__ float2 cmul(float2 a, float2 b) {
    return make_float2(a.x * b.x - a.y * b.y, a.x * b.y + a.y * b.x);
}
__device__ __forceinline__ unsigned pack_f16(float a, float b) {
    __half2 h = __floats2half2_rn(a, b);
    return *(unsigned*)&h;
}
__device__ __forceinline__ void mma_f16(float c[4], const unsigned a[4], unsigned b0, unsigned b1) {
    asm volatile(
        "mma.sync.aligned.m16n8k16.row.col.f32.f16.f16.f32 "
        "{%0,%1,%2,%3}, {%4,%5,%6,%7}, {%8,%9}, {%0,%1,%2,%3};"
        : "+f"(c[0]), "+f"(c[1]), "+f"(c[2]), "+f"(c[3])
        : "r"(a[0]), "r"(a[1]), "r"(a[2]), "r"(a[3]), "r"(b0), "r"(b1));
}
__device__ __forceinline__ void ldsm_x4_t(unsigned r[4], unsigned addr) {
    asm volatile("ldmatrix.sync.aligned.m8n8.x4.trans.shared.b16 {%0,%1,%2,%3}, [%4];"
                 : "=r"(r[0]), "=r"(r[1]), "=r"(r[2]), "=r"(r[3]) : "r"(addr));
}
__device__ __forceinline__ unsigned smem_u32(const void* p) {
    unsigned a;
    asm("{ .reg .u64 t; cvta.to.shared.u64 t, %1; cvt.u32.u64 %0, t; }" : "=r"(a) : "l"(p));
    return a;
}

// ---------------------------------------------------------------------------
// K0: pack weights (fp16) + seed scan sentinels.
// ---------------------------------------------------------------------------
__device__ __forceinline__ float wb_get(int r, int c, const float* Bre, const float* Bim) {
    return (r < 256) ? Bre[r * 128 + c] : Bim[(r - 256) * 128 + c];
}
__device__ __forceinline__ float wc_get(int o, int k, const float* Cre, const float* Cim,
                                        const float* Dm) {
    if (k < 256) return Cre[o * 256 + k];
    if (k < 512) return -Cim[o * 256 + (k - 256)];
    return Dm[o * 128 + (k - 512)];
}
__global__ void __launch_bounds__(256) k0_prep(
    const float* __restrict__ Bre, const float* __restrict__ Bim,
    const float* __restrict__ Cre, const float* __restrict__ Cim,
    const float* __restrict__ Dm)
{
    int idx = blockIdx.x * 256 + threadIdx.x;
    for (int j = idx; j < BSZ * NC2 * PD; j += gridDim.x * 256)
        g_S[j] = (unsigned long long)SENT;
    if (idx < 32 * 8 * 32) {
        int lane = idx & 31, ks = (idx >> 5) & 7, blk = idx >> 8;
        int r = blk * 16 + (lane >> 2);
        int cb = ks * 16 + (lane & 3) * 2;
        uint4 o;
        o.x = pack_f16(wb_get(r,     cb,     Bre, Bim), wb_get(r,     cb + 1, Bre, Bim));
        o.y = pack_f16(wb_get(r + 8, cb,     Bre, Bim), wb_get(r + 8, cb + 1, Bre, Bim));
        o.z = pack_f16(wb_get(r,     cb + 8, Bre, Bim), wb_get(r,     cb + 9, Bre, Bim));
        o.w = pack_f16(wb_get(r + 8, cb + 8, Bre, Bim), wb_get(r + 8, cb + 9, Bre, Bim));
        g_WbPk[idx] = o;
    }
    if (idx < 8 * 40 * 32) {
        int lane = idx & 31, t = idx >> 5;
        int ks = t % 40, blk = t / 40;
        int r = blk * 16 + (lane >> 2);
        int cb = ks * 16 + (lane & 3) * 2;
        uint4 o;
        o.x = pack_f16(wc_get(r,     cb,     Cre, Cim, Dm), wc_get(r,     cb + 1, Cre, Cim, Dm));
        o.y = pack_f16(wc_get(r + 8, cb,     Cre, Cim, Dm), wc_get(r + 8, cb + 1, Cre, Cim, Dm));
        o.z = pack_f16(wc_get(r,     cb + 8, Cre, Cim, Dm), wc_get(r,     cb + 9, Cre, Cim, Dm));
        o.w = pack_f16(wc_get(r + 8, cb + 8, Cre, Cim, Dm), wc_get(r + 8, cb + 9, Cre, Cim, Dm));
        g_WcPk[idx] = o;
    }
}

// ---------------------------------------------------------------------------
// mma over staged [NKS*16 k][n] fp16 tile, SR = padded row stride.
// c is [2 * 2*NGS][4]: index (mi * 2*NGS + ng*2 + half).
// ---------------------------------------------------------------------------
template<int NKS, int NGS, int SR>
__device__ __forceinline__ void mma_block(float (*c)[4], const uint4* wpk, int ks_stride,
                                          int blk0, int blk1, int ksg0,
                                          unsigned s_base, int lane, int nwbase)
{
    const int brow = (lane & 7) + (lane & 8);
    const int bcol = ((lane >> 4) << 3);
#pragma unroll
    for (int ks = 0; ks < NKS; ks++) {
        const int km = ks * 16;
        const int ksg = ksg0 + ks;
        uint4 ah0 = wpk[(blk0 * ks_stride + ksg) * 32 + lane];
        uint4 ah1 = wpk[(blk1 * ks_stride + ksg) * 32 + lane];
#pragma unroll
        for (int ng = 0; ng < NGS; ng++) {
            int n0 = nwbase + ng * 16;
            unsigned off = (unsigned)(((km + brow) * SR + n0 + bcol) * 2);
            unsigned bb[4];
            ldsm_x4_t(bb, s_base + off);
            mma_f16(c[0 * 2 * NGS + ng * 2 + 0], (const unsigned*)&ah0, bb[0], bb[1]);
            mma_f16(c[0 * 2 * NGS + ng * 2 + 1], (const unsigned*)&ah0, bb[2], bb[3]);
            mma_f16(c[1 * 2 * NGS + ng * 2 + 0], (const unsigned*)&ah1, bb[0], bb[1]);
            mma_f16(c[1 * 2 * NGS + ng * 2 + 1], (const unsigned*)&ah1, bb[2], bb[3]);
        }
    }
}

// ---------------------------------------------------------------------------
// K1: [Bre;Bim](512x128) @ u(128 x L) -> fp16 planar g_brh/g_bih.
// l-tile = 64 for occupancy: grid (L/64, 1, BSZ) = 1024 CTAs, 3 CTA/SM.
// Stages full K=128 x 64 l fp16 tile (18.4 KB), loops 4 m-tiles.
// ---------------------------------------------------------------------------
#define SR1 72

__global__ void __launch_bounds__(256, 3) k1_bu(const float* __restrict__ u)
{
    __shared__ __align__(16) __half sh[128][SR1];

    const int b = blockIdx.z, lbase = blockIdx.x * 64;
    const int tid = threadIdx.x, lane = tid & 31, wid = tid >> 5;
    const int wm = wid >> 1, wn = wid & 1;
    const unsigned s_base = smem_u32(&sh[0][0]);

    // stage 128k x 64l fp32 -> fp16
    {
        const int row = tid >> 1, half = tid & 1;
        const float* s = u + ((size_t)b * HD + row) * LSEQ + lbase + half * 32;
#pragma unroll
        for (int q = 0; q < 4; q++) {
            float4 v0 = *(const float4*)(s + q * 8);
            float4 v1 = *(const float4*)(s + q * 8 + 4);
            uint4 pk;
            pk.x = pack_f16(v0.x, v0.y); pk.y = pack_f16(v0.z, v0.w);
            pk.z = pack_f16(v1.x, v1.y); pk.w = pack_f16(v1.z, v1.w);
            *(uint4*)&sh[row][half * 32 + q * 8] = pk;
        }
    }
    __syncthreads();

#pragma unroll 1
    for (int mt = 0; mt < 4; mt++) {
        float c[8][4];
#pragma unroll
        for (int i = 0; i < 8; i++)
#pragma unroll
            for (int q = 0; q < 4; q++) c[i][q] = 0.f;

        const int blk0 = mt * 8 + wm * 2;
        mma_block<8, 2, SR1>(c, g_WbPk, 8, blk0, blk0 + 1, 0, s_base, lane, wn * 32);

#pragma unroll
        for (int mi = 0; mi < 2; mi++) {
#pragma unroll
            for (int ni = 0; ni < 4; ni++) {
                const float* cc = c[mi * 4 + ni];
                int r0  = mt * 128 + wm * 32 + mi * 16 + (lane >> 2);
                int col = lbase + wn * 32 + ni * 8 + (lane & 3) * 2;
                {
                    __half* plane = (r0 < 256) ? g_brh : g_bih;
                    int pr = (r0 < 256) ? r0 : r0 - 256;
                    __half2 h = __floats2half2_rn(cc[0], cc[1]);
                    *(__half2*)&plane[((size_t)b * PD + pr) * LSEQ + col] = h;
                }
                int r1 = r0 + 8;
                {
                    __half* plane = (r1 < 256) ? g_brh : g_bih;
                    int pr = (r1 < 256) ? r1 : r1 - 256;
                    __half2 h = __floats2half2_rn(cc[2], cc[3]);
                    *(__half2*)&plane[((size_t)b * PD + pr) * LSEQ + col] = h;
                }
            }
        }
    }
}

// ---------------------------------------------------------------------------
// K2: single-pass chained scan (proven in R12).
// ---------------------------------------------------------------------------
__device__ __forceinline__ void lane_powers(float2 a, int lane, float2* ap, float2* w1m)
{
    float invn = 1.f / (a.x * a.x + a.y * a.y);
    float2 ainv = make_float2(a.x * invn, -a.y * invn);
    float2 pp = make_float2(1.f, 0.f), pn = make_float2(1.f, 0.f);
    float2 t = a, ti = ainv;
#pragma unroll
    for (int bit = 1; bit < 32; bit <<= 1) {
        if (lane & bit) { pp = cmul(pp, t); pn = cmul(pn, ti); }
        t = cmul(t, t); ti = cmul(ti, ti);
    }
    *ap = pp; *w1m = cmul(a, pn);
}

__global__ void __launch_bounds__(256) k2_scan(
    const float* __restrict__ Are, const float* __restrict__ Aim)
{
    const int pg = blockIdx.x, b = blockIdx.y, c = blockIdx.z;
    const int wid = threadIdx.x >> 5, lane = threadIdx.x & 31;
    const int p = pg * 8 + wid;
    const float2 a = make_float2(Are[p], Aim[p]);
    float2 ap, w1m;
    lane_powers(a, lane, &ap, &w1m);
    float2 a32 = a;
#pragma unroll
    for (int k = 0; k < 5; k++) a32 = cmul(a32, a32);
    float2 a512 = a32;
#pragma unroll
    for (int k = 0; k < 4; k++) a512 = cmul(a512, a512);

    const size_t base = ((size_t)b * PD + p) * LSEQ + (size_t)c * CL;

    float2 X[16];
    float2 carry = make_float2(0.f, 0.f);
#pragma unroll
    for (int s = 0; s < 16; s++) {
        size_t idx = base + s * 32 + lane;
        float br = __half2float(g_brh[idx]);
        float bi = __half2float(g_bih[idx]);
        float2 w = make_float2(br * w1m.x - bi * w1m.y, br * w1m.y + bi * w1m.x);
#pragma unroll
        for (int d = 1; d < 32; d <<= 1) {
            float ox = __shfl_up_sync(0xffffffffu, w.x, d);
            float oy = __shfl_up_sync(0xffffffffu, w.y, d);
            if (lane >= d) { w.x += ox; w.y += oy; }
        }
        float2 ac = cmul(a, carry);
        float2 x  = cmul(ap, make_float2(ac.x + w.x, ac.y + w.y));
        X[s] = x;
        carry.x = __shfl_sync(0xffffffffu, x.x, 31);
        carry.y = __shfl_sync(0xffffffffu, x.y, 31);
    }

    const int sidx = (b * NC2 + c) * PD + p;
    float2 C0 = make_float2(0.f, 0.f);
    if (lane == 0) {
        if (c > 0) {
            unsigned long long v;
            while (true) {
                asm volatile("ld.acquire.gpu.global.b64 %0, [%1];"
                             : "=l"(v) : "l"(g_S + sidx - PD) : "memory");
                if ((unsigned)v != SENT) break;
                __nanosleep(64);
            }
            C0.x = __uint_as_float((unsigned)v);
            C0.y = __uint_as_float((unsigned)(v >> 32));
        }
        float2 Et = make_float2(carry.x + a512.x * C0.x - a512.y * C0.y,
                                carry.y + a512.x * C0.y + a512.y * C0.x);
        unsigned long long pub = (unsigned long long)__float_as_uint(Et.x)
                               | ((unsigned long long)__float_as_uint(Et.y) << 32);
        asm volatile("st.release.gpu.global.b64 [%0], %1;"
                     :: "l"(g_S + sidx), "l"(pub) : "memory");
    }
    C0.x = __shfl_sync(0xffffffffu, C0.x, 0);
    C0.y = __shfl_sync(0xffffffffu, C0.y, 0);

    float2 Ck = cmul(cmul(a, ap), C0);
#pragma unroll
    for (int s = 0; s < 16; s++) {
        size_t idx = base + s * 32 + lane;
        g_xr[idx] = __float2half_rn(X[s].x + Ck.x);
        g_xi[idx] = __float2half_rn(X[s].y + Ck.y);
        Ck = cmul(Ck, a32);
    }
}

// ---------------------------------------------------------------------------
// K3: [Cre|-Cim|D](128x640) @ [x_re;x_im;u](640 x L) + GELU.
// l-tile = 64, target 4 CTA/SM. Double-buffered smem, one sync per chunk.
// ---------------------------------------------------------------------------
#define SR3 72

__global__ void __launch_bounds__(256, 4) k3_out(const float* __restrict__ u,
                                                 float* __restrict__ out)
{
    __shared__ __align__(16) __half sh[2][64][SR3];

    const int b = blockIdx.y, lbase = blockIdx.x * 64;
    const int tid = threadIdx.x, lane = tid & 31, wid = tid >> 5;
    const int wm = wid >> 1, wn = wid & 1;
    const unsigned s_base0 = smem_u32(&sh[0][0][0]);
    const unsigned s_base1 = smem_u32(&sh[1][0][0]);
    const int row = tid >> 2, quarter = tid & 3;

    float c[8][4];
#pragma unroll
    for (int i = 0; i < 8; i++)
#pragma unroll
        for (int q = 0; q < 4; q++) c[i][q] = 0.f;

    uint4 pv[4];

    auto prefetch = [&](int cc) {
        if (cc < 8) {
            const __half* src = (cc >= 4) ? g_xi : g_xr;
            const uint4* s = (const uint4*)(src +
                ((size_t)b * PD + (cc & 3) * 64 + row) * LSEQ + lbase + quarter * 16);
#pragma unroll
            for (int q = 0; q < 2; q++) pv[q] = s[q];
        } else {
            const uint4* s = (const uint4*)(u +
                ((size_t)b * HD + (cc - 8) * 64 + row) * LSEQ + lbase + quarter * 16);
#pragma unroll
            for (int q = 0; q < 4; q++) pv[q] = s[q];
        }
    };
    auto stage_store = [&](int cc, int buf) {
        if (cc < 8) {
#pragma unroll
            for (int q = 0; q < 2; q++)
                *(uint4*)&sh[buf][row][quarter * 16 + q * 8] = pv[q];
        } else {
#pragma unroll
            for (int q = 0; q < 2; q++) {
                float4 v0 = *(float4*)&pv[2 * q];
                float4 v1 = *(float4*)&pv[2 * q + 1];
                uint4 pk;
                pk.x = pack_f16(v0.x, v0.y); pk.y = pack_f16(v0.z, v0.w);
                pk.z = pack_f16(v1.x, v1.y); pk.w = pack_f16(v1.z, v1.w);
                *(uint4*)&sh[buf][row][quarter * 16 + q * 8] = pk;
            }
        }
    };

    prefetch(0);
    stage_store(0, 0);
    __syncthreads();

    const int blk0 = wm * 2;
#pragma unroll 1
    for (int cc = 0; cc < 10; cc++) {
        if (cc < 9) prefetch(cc + 1);
        mma_block<4, 2, SR3>(c, g_WcPk, 40, blk0, blk0 + 1, cc * 4,
                             (cc & 1) ? s_base1 : s_base0, lane, wn * 32);
        if (cc < 9) stage_store(cc + 1, (cc + 1) & 1);
        __syncthreads();
    }

#pragma unroll
    for (int mi = 0; mi < 2; mi++) {
#pragma unroll
        for (int ni = 0; ni < 4; ni++) {
            const float* cc = c[mi * 4 + ni];
            int r0  = wm * 32 + mi * 16 + (lane >> 2);
            int col = lbase + wn * 32 + ni * 8 + (lane & 3) * 2;
            float y0 = cc[0], y1 = cc[1], y2 = cc[2], y3 = cc[3];
            y0 = 0.5f * y0 * (1.f + erff(y0 * 0.70710678118654752f));
            y1 = 0.5f * y1 * (1.f + erff(y1 * 0.70710678118654752f));
            y2 = 0.5f * y2 * (1.f + erff(y2 * 0.70710678118654752f));
            y3 = 0.5f * y3 * (1.f + erff(y3 * 0.70710678118654752f));
            *(float2*)&out[((size_t)b * HD + r0) * LSEQ + col]     = make_float2(y0, y1);
            *(float2*)&out[((size_t)b * HD + r0 + 8) * LSEQ + col] = make_float2(y2, y3);
        }
    }
}

// ---------------------------------------------------------------------------
extern "C" void kernel_launch(void* const* d_in, const int* in_sizes, int n_in,
                              void* d_out, int out_size)
{
    (void)in_sizes; (void)n_in; (void)out_size;
    const float* u   = (const float*)d_in[0];
    const float* Are = (const float*)d_in[1];
    const float* Aim = (const float*)d_in[2];
    const float* Bre = (const float*)d_in[3];
    const float* Bim = (const float*)d_in[4];
    const float* Cre = (const float*)d_in[5];
    const float* Cim = (const float*)d_in[6];
    const float* Dm  = (const float*)d_in[7];
    float* out = (float*)d_out;

    k0_prep <<<80, 256>>>(Bre, Bim, Cre, Cim, Dm);
    k1_bu   <<<dim3(LSEQ / 64, 1, BSZ), 256>>>(u);
    k2_scan <<<dim3(PD / 8, BSZ, NC2), 256>>>(Are, Aim);
    k3_out  <<<dim3(LSEQ / 64, BSZ), 256>>>(u, out);
}

// round 15
// speedup vs baseline: 1.1236x; 1.1236x over previous
#include <cuda_runtime.h>
#include <cuda_fp16.h>
#include <math.h>
#include <stdint.h>

#define BSZ   8
#define HD    128
#define LSEQ  8192
#define PD    256
#define NC2   16
#define CL    (LSEQ / NC2)   // 512
#define SENT  0x7FC00001u    // NaN-payload sentinel ("not published")

// ---------------- scratch ----------------
__device__ __align__(16) __half g_brh[(size_t)BSZ * PD * LSEQ];  // Bu real (planar b,p,l) fp16
__device__ __align__(16) __half g_bih[(size_t)BSZ * PD * LSEQ];  // Bu imag
__device__ __align__(16) __half g_xr[(size_t)BSZ * PD * LSEQ];   // x real (fp16)
__device__ __align__(16) __half g_xi[(size_t)BSZ * PD * LSEQ];   // x imag (fp16)
__device__ __align__(8) unsigned long long g_S[BSZ * NC2 * PD];  // packed chunk-end states
// Packed per-lane mma A-fragments (fp16): [m16blk][ks][lane]
__device__ __align__(16) uint4 g_WbPk[32 * 8 * 32];    // Wb: M=512, K=128
__device__ __align__(16) uint4 g_WcPk[8 * 40 * 32];    // Wc: M=128, K=640

__device__ __forceinline__ float2 cmul(float2 a, float2 b) {
    return make_float2(a.x * b.x - a.y * b.y, a.x * b.y + a.y * b.x);
}
__device__ __forceinline__ unsigned pack_f16(float a, float b) {
    __half2 h = __floats2half2_rn(a, b);
    return *(unsigned*)&h;
}
__device__ __forceinline__ void mma_f16(float c[4], const unsigned a[4], unsigned b0, unsigned b1) {
    asm volatile(
        "mma.sync.aligned.m16n8k16.row.col.f32.f16.f16.f32 "
        "{%0,%1,%2,%3}, {%4,%5,%6,%7}, {%8,%9}, {%0,%1,%2,%3};"
        : "+f"(c[0]), "+f"(c[1]), "+f"(c[2]), "+f"(c[3])
        : "r"(a[0]), "r"(a[1]), "r"(a[2]), "r"(a[3]), "r"(b0), "r"(b1));
}
__device__ __forceinline__ void ldsm_x4_t(unsigned r[4], unsigned addr) {
    asm volatile("ldmatrix.sync.aligned.m8n8.x4.trans.shared.b16 {%0,%1,%2,%3}, [%4];"
                 : "=r"(r[0]), "=r"(r[1]), "=r"(r[2]), "=r"(r[3]) : "r"(addr));
}
__device__ __forceinline__ unsigned smem_u32(const void* p) {
    unsigned a;
    asm("{ .reg .u64 t; cvta.to.shared.u64 t, %1; cvt.u32.u64 %0, t; }" : "=r"(a) : "l"(p));
    return a;
}

// ---------------------------------------------------------------------------
// K0: pack weights (fp16) + seed scan sentinels.
// ---------------------------------------------------------------------------
__device__ __forceinline__ float wb_get(int r, int c, const float* Bre, const float* Bim) {
    return (r < 256) ? Bre[r * 128 + c] : Bim[(r - 256) * 128 + c];
}
__device__ __forceinline__ float wc_get(int o, int k, const float* Cre, const float* Cim,
                                        const float* Dm) {
    if (k < 256) return Cre[o * 256 + k];
    if (k < 512) return -Cim[o * 256 + (k - 256)];
    return Dm[o * 128 + (k - 512)];
}
__global__ void __launch_bounds__(256) k0_prep(
    const float* __restrict__ Bre, const float* __restrict__ Bim,
    const float* __restrict__ Cre, const float* __restrict__ Cim,
    const float* __restrict__ Dm)
{
    int idx = blockIdx.x * 256 + threadIdx.x;
    for (int j = idx; j < BSZ * NC2 * PD; j += gridDim.x * 256)
        g_S[j] = (unsigned long long)SENT;
    if (idx < 32 * 8 * 32) {
        int lane = idx & 31, ks = (idx >> 5) & 7, blk = idx >> 8;
        int r = blk * 16 + (lane >> 2);
        int cb = ks * 16 + (lane & 3) * 2;
        uint4 o;
        o.x = pack_f16(wb_get(r,     cb,     Bre, Bim), wb_get(r,     cb + 1, Bre, Bim));
        o.y = pack_f16(wb_get(r + 8, cb,     Bre, Bim), wb_get(r + 8, cb + 1, Bre, Bim));
        o.z = pack_f16(wb_get(r,     cb + 8, Bre, Bim), wb_get(r,     cb + 9, Bre, Bim));
        o.w = pack_f16(wb_get(r + 8, cb + 8, Bre, Bim), wb_get(r + 8, cb + 9, Bre, Bim));
        g_WbPk[idx] = o;
    }
    if (idx < 8 * 40 * 32) {
        int lane = idx & 31, t = idx >> 5;
        int ks = t % 40, blk = t / 40;
        int r = blk * 16 + (lane >> 2);
        int cb = ks * 16 + (lane & 3) * 2;
        uint4 o;
        o.x = pack_f16(wc_get(r,     cb,     Cre, Cim, Dm), wc_get(r,     cb + 1, Cre, Cim, Dm));
        o.y = pack_f16(wc_get(r + 8, cb,     Cre, Cim, Dm), wc_get(r + 8, cb + 1, Cre, Cim, Dm));
        o.z = pack_f16(wc_get(r,     cb + 8, Cre, Cim, Dm), wc_get(r,     cb + 9, Cre, Cim, Dm));
        o.w = pack_f16(wc_get(r + 8, cb + 8, Cre, Cim, Dm), wc_get(r + 8, cb + 9, Cre, Cim, Dm));
        g_WcPk[idx] = o;
    }
}

// ---------------------------------------------------------------------------
// mma over staged [NKS*16 k][n] fp16 tile, SR = padded row stride.
// ---------------------------------------------------------------------------
template<int NKS, int NGS, int SR>
__device__ __forceinline__ void mma_block(float (*c)[4], const uint4* wpk, int ks_stride,
                                          int blk0, int blk1, int ksg0,
                                          unsigned s_base, int lane, int nwbase)
{
    const int brow = (lane & 7) + (lane & 8);
    const int bcol = ((lane >> 4) << 3);
#pragma unroll
    for (int ks = 0; ks < NKS; ks++) {
        const int km = ks * 16;
        const int ksg = ksg0 + ks;
        uint4 ah0 = wpk[(blk0 * ks_stride + ksg) * 32 + lane];
        uint4 ah1 = wpk[(blk1 * ks_stride + ksg) * 32 + lane];
#pragma unroll
        for (int ng = 0; ng < NGS; ng++) {
            int n0 = nwbase + ng * 16;
            unsigned off = (unsigned)(((km + brow) * SR + n0 + bcol) * 2);
            unsigned bb[4];
            ldsm_x4_t(bb, s_base + off);
            mma_f16(c[0 * 2 * NGS + ng * 2 + 0], (const unsigned*)&ah0, bb[0], bb[1]);
            mma_f16(c[0 * 2 * NGS + ng * 2 + 1], (const unsigned*)&ah0, bb[2], bb[3]);
            mma_f16(c[1 * 2 * NGS + ng * 2 + 0], (const unsigned*)&ah1, bb[0], bb[1]);
            mma_f16(c[1 * 2 * NGS + ng * 2 + 1], (const unsigned*)&ah1, bb[2], bb[3]);
        }
    }
}

// ---------------------------------------------------------------------------
// K1: [Bre;Bim](512x128) @ u(128 x L) -> fp16 planar. l-tile 64, 3 CTA/SM.
// ---------------------------------------------------------------------------
#define SR1 72

__global__ void __launch_bounds__(256, 3) k1_bu(const float* __restrict__ u)
{
    __shared__ __align__(16) __half sh[128][SR1];

    const int b = blockIdx.z, lbase = blockIdx.x * 64;
    const int tid = threadIdx.x, lane = tid & 31, wid = tid >> 5;
    const int wm = wid >> 1, wn = wid & 1;
    const unsigned s_base = smem_u32(&sh[0][0]);

    {
        const int row = tid >> 1, half = tid & 1;
        const float* s = u + ((size_t)b * HD + row) * LSEQ + lbase + half * 32;
#pragma unroll
        for (int q = 0; q < 4; q++) {
            float4 v0 = *(const float4*)(s + q * 8);
            float4 v1 = *(const float4*)(s + q * 8 + 4);
            uint4 pk;
            pk.x = pack_f16(v0.x, v0.y); pk.y = pack_f16(v0.z, v0.w);
            pk.z = pack_f16(v1.x, v1.y); pk.w = pack_f16(v1.z, v1.w);
            *(uint4*)&sh[row][half * 32 + q * 8] = pk;
        }
    }
    __syncthreads();

#pragma unroll 1
    for (int mt = 0; mt < 4; mt++) {
        float c[8][4];
#pragma unroll
        for (int i = 0; i < 8; i++)
#pragma unroll
            for (int q = 0; q < 4; q++) c[i][q] = 0.f;

        const int blk0 = mt * 8 + wm * 2;
        mma_block<8, 2, SR1>(c, g_WbPk, 8, blk0, blk0 + 1, 0, s_base, lane, wn * 32);

#pragma unroll
        for (int mi = 0; mi < 2; mi++) {
#pragma unroll
            for (int ni = 0; ni < 4; ni++) {
                const float* cc = c[mi * 4 + ni];
                int r0  = mt * 128 + wm * 32 + mi * 16 + (lane >> 2);
                int col = lbase + wn * 32 + ni * 8 + (lane & 3) * 2;
                {
                    __half* plane = (r0 < 256) ? g_brh : g_bih;
                    int pr = (r0 < 256) ? r0 : r0 - 256;
                    __half2 h = __floats2half2_rn(cc[0], cc[1]);
                    *(__half2*)&plane[((size_t)b * PD + pr) * LSEQ + col] = h;
                }
                int r1 = r0 + 8;
                {
                    __half* plane = (r1 < 256) ? g_brh : g_bih;
                    int pr = (r1 < 256) ? r1 : r1 - 256;
                    __half2 h = __floats2half2_rn(cc[2], cc[3]);
                    *(__half2*)&plane[((size_t)b * PD + pr) * LSEQ + col] = h;
                }
            }
        }
    }
}

// ---------------------------------------------------------------------------
// K2: single-pass chained BLOCKED scan. Lane owns 16 consecutive l.
// Serial in-register recurrence, one warp scan over lane carries (factor a^16),
// fused fix-up (intra-warp carry + a^(16*lane)*C0). Vectorized 16B ld/st.
// Chain protocol identical to R12 (release/acquire packed 64-bit word).
// ---------------------------------------------------------------------------
__global__ void __launch_bounds__(256) k2_scan(
    const float* __restrict__ Are, const float* __restrict__ Aim)
{
    const int pg = blockIdx.x, b = blockIdx.y, c = blockIdx.z;
    const int wid = threadIdx.x >> 5, lane = threadIdx.x & 31;
    const int p = pg * 8 + wid;
    const float2 a = make_float2(Are[p], Aim[p]);

    // g = a^16
    float2 g = a;
#pragma unroll
    for (int k = 0; k < 4; k++) g = cmul(g, g);

    // gt = g^lane (binary); t2 ends at g^32 = a^512
    float2 gt = make_float2(1.f, 0.f), t2 = g;
#pragma unroll
    for (int bit = 1; bit < 32; bit <<= 1) {
        if (lane & bit) gt = cmul(gt, t2);
        t2 = cmul(t2, t2);
    }
    const float2 a512 = t2;

    const size_t base = ((size_t)b * PD + p) * LSEQ + (size_t)c * CL + lane * 16;

    __half2 hr[8], hi[8];
    *(uint4*)&hr[0] = *(const uint4*)(g_brh + base);
    *(uint4*)&hr[4] = *(const uint4*)(g_brh + base + 8);
    *(uint4*)&hi[0] = *(const uint4*)(g_bih + base);
    *(uint4*)&hi[4] = *(const uint4*)(g_bih + base + 8);

    // serial local scan over 16 elements
    float2 X[16];
    float2 x = make_float2(0.f, 0.f);
#pragma unroll
    for (int j = 0; j < 16; j++) {
        float2 rr = __half22float2(hr[j >> 1]);
        float2 ii = __half22float2(hi[j >> 1]);
        float br = (j & 1) ? rr.y : rr.x;
        float bi = (j & 1) ? ii.y : ii.x;
        float2 s = make_float2(x.x + br, x.y + bi);
        x = cmul(a, s);
        X[j] = x;
    }

    // warp inclusive scan over lane end-states with multiplier g = a^16
    float2 v = x;
    float2 gd = g;
#pragma unroll
    for (int d = 1; d < 32; d <<= 1) {
        float ox = __shfl_up_sync(0xffffffffu, v.x, d);
        float oy = __shfl_up_sync(0xffffffffu, v.y, d);
        if (lane >= d) {
            v.x += gd.x * ox - gd.y * oy;
            v.y += gd.x * oy + gd.y * ox;
        }
        gd = cmul(gd, gd);
    }
    float cux = __shfl_up_sync(0xffffffffu, v.x, 1);
    float cuy = __shfl_up_sync(0xffffffffu, v.y, 1);
    float2 Cth = (lane == 0) ? make_float2(0.f, 0.f) : make_float2(cux, cuy);
    float2 Eloc = make_float2(__shfl_sync(0xffffffffu, v.x, 31),
                              __shfl_sync(0xffffffffu, v.y, 31));

    // chain: acquire predecessor's state, publish own (R12-proven protocol)
    const int sidx = (b * NC2 + c) * PD + p;
    float2 C0 = make_float2(0.f, 0.f);
    if (lane == 0) {
        if (c > 0) {
            unsigned long long w;
            while (true) {
                asm volatile("ld.acquire.gpu.global.b64 %0, [%1];"
                             : "=l"(w) : "l"(g_S + sidx - PD) : "memory");
                if ((unsigned)w != SENT) break;
                __nanosleep(64);
            }
            C0.x = __uint_as_float((unsigned)w);
            C0.y = __uint_as_float((unsigned)(w >> 32));
        }
        float2 Et = make_float2(Eloc.x + a512.x * C0.x - a512.y * C0.y,
                                Eloc.y + a512.x * C0.y + a512.y * C0.x);
        unsigned long long pub = (unsigned long long)__float_as_uint(Et.x)
                               | ((unsigned long long)__float_as_uint(Et.y) << 32);
        asm volatile("st.release.gpu.global.b64 [%0], %1;"
                     :: "l"(g_S + sidx), "l"(pub) : "memory");
    }
    C0.x = __shfl_sync(0xffffffffu, C0.x, 0);
    C0.y = __shfl_sync(0xffffffffu, C0.y, 0);

    // total carry into this lane's segment: Cth + g^lane * C0
    float2 Ct = make_float2(Cth.x + gt.x * C0.x - gt.y * C0.y,
                            Cth.y + gt.x * C0.y + gt.y * C0.x);

    // fix-up: X[j] += a^(j+1) * Ct
    float2 ck = cmul(a, Ct);
#pragma unroll
    for (int j = 0; j < 16; j++) {
        X[j].x += ck.x; X[j].y += ck.y;
        if (j < 15) ck = cmul(ck, a);
    }

    // pack & vectorized store
    __half2 orr[8], ori[8];
#pragma unroll
    for (int j = 0; j < 8; j++) {
        orr[j] = __floats2half2_rn(X[2 * j].x, X[2 * j + 1].x);
        ori[j] = __floats2half2_rn(X[2 * j].y, X[2 * j + 1].y);
    }
    *(uint4*)(g_xr + base)     = *(uint4*)&orr[0];
    *(uint4*)(g_xr + base + 8) = *(uint4*)&orr[4];
    *(uint4*)(g_xi + base)     = *(uint4*)&ori[0];
    *(uint4*)(g_xi + base + 8) = *(uint4*)&ori[4];
}

// ---------------------------------------------------------------------------
// K3: [Cre|-Cim|D](128x640) @ [x_re;x_im;u](640 x L) + GELU.
// l-tile 64, 3 CTA/SM (R13-proven). Double-buffered, one sync per chunk.
// ---------------------------------------------------------------------------
#define SR3 72

__global__ void __launch_bounds__(256, 3) k3_out(const float* __restrict__ u,
                                                 float* __restrict__ out)
{
    __shared__ __align__(16) __half sh[2][64][SR3];

    const int b = blockIdx.y, lbase = blockIdx.x * 64;
    const int tid = threadIdx.x, lane = tid & 31, wid = tid >> 5;
    const int wm = wid >> 1, wn = wid & 1;
    const unsigned s_base0 = smem_u32(&sh[0][0][0]);
    const unsigned s_base1 = smem_u32(&sh[1][0][0]);
    const int row = tid >> 2, quarter = tid & 3;

    float c[8][4];
#pragma unroll
    for (int i = 0; i < 8; i++)
#pragma unroll
        for (int q = 0; q < 4; q++) c[i][q] = 0.f;

    uint4 pv[4];

    auto prefetch = [&](int cc) {
        if (cc < 8) {
            const __half* src = (cc >= 4) ? g_xi : g_xr;
            const uint4* s = (const uint4*)(src +
                ((size_t)b * PD + (cc & 3) * 64 + row) * LSEQ + lbase + quarter * 16);
#pragma unroll
            for (int q = 0; q < 2; q++) pv[q] = s[q];
        } else {
            const uint4* s = (const uint4*)(u +
                ((size_t)b * HD + (cc - 8) * 64 + row) * LSEQ + lbase + quarter * 16);
#pragma unroll
            for (int q = 0; q < 4; q++) pv[q] = s[q];
        }
    };
    auto stage_store = [&](int cc, int buf) {
        if (cc < 8) {
#pragma unroll
            for (int q = 0; q < 2; q++)
                *(uint4*)&sh[buf][row][quarter * 16 + q * 8] = pv[q];
        } else {
#pragma unroll
            for (int q = 0; q < 2; q++) {
                float4 v0 = *(float4*)&pv[2 * q];
                float4 v1 = *(float4*)&pv[2 * q + 1];
                uint4 pk;
                pk.x = pack_f16(v0.x, v0.y); pk.y = pack_f16(v0.z, v0.w);
                pk.z = pack_f16(v1.x, v1.y); pk.w = pack_f16(v1.z, v1.w);
                *(uint4*)&sh[buf][row][quarter * 16 + q * 8] = pk;
            }
        }
    };

    prefetch(0);
    stage_store(0, 0);
    __syncthreads();

    const int blk0 = wm * 2;
#pragma unroll 1
    for (int cc = 0; cc < 10; cc++) {
        if (cc < 9) prefetch(cc + 1);
        mma_block<4, 2, SR3>(c, g_WcPk, 40, blk0, blk0 + 1, cc * 4,
                             (cc & 1) ? s_base1 : s_base0, lane, wn * 32);
        if (cc < 9) stage_store(cc + 1, (cc + 1) & 1);
        __syncthreads();
    }

#pragma unroll
    for (int mi = 0; mi < 2; mi++) {
#pragma unroll
        for (int ni = 0; ni < 4; ni++) {
            const float* cc = c[mi * 4 + ni];
            int r0  = wm * 32 + mi * 16 + (lane >> 2);
            int col = lbase + wn * 32 + ni * 8 + (lane & 3) * 2;
            float y0 = cc[0], y1 = cc[1], y2 = cc[2], y3 = cc[3];
            y0 = 0.5f * y0 * (1.f + erff(y0 * 0.70710678118654752f));
            y1 = 0.5f * y1 * (1.f + erff(y1 * 0.70710678118654752f));
            y2 = 0.5f * y2 * (1.f + erff(y2 * 0.70710678118654752f));
            y3 = 0.5f * y3 * (1.f + erff(y3 * 0.70710678118654752f));
            *(float2*)&out[((size_t)b * HD + r0) * LSEQ + col]     = make_float2(y0, y1);
            *(float2*)&out[((size_t)b * HD + r0 + 8) * LSEQ + col] = make_float2(y2, y3);
        }
    }
}

// ---------------------------------------------------------------------------
extern "C" void kernel_launch(void* const* d_in, const int* in_sizes, int n_in,
                              void* d_out, int out_size)
{
    (void)in_sizes; (void)n_in; (void)out_size;
    const float* u   = (const float*)d_in[0];
    const float* Are = (const float*)d_in[1];
    const float* Aim = (const float*)d_in[2];
    const float* Bre = (const float*)d_in[3];
    const float* Bim = (const float*)d_in[4];
    const float* Cre = (const float*)d_in[5];
    const float* Cim = (const float*)d_in[6];
    const float* Dm  = (const float*)d_in[7];
    float* out = (float*)d_out;

    k0_prep <<<80, 256>>>(Bre, Bim, Cre, Cim, Dm);
    k1_bu   <<<dim3(LSEQ / 64, 1, BSZ), 256>>>(u);
    k2_scan <<<dim3(PD / 8, BSZ, NC2), 256>>>(Are, Aim);
    k3_out  <<<dim3(LSEQ / 64, BSZ), 256>>>(u, out);
}

// round 16
// speedup vs baseline: 1.1357x; 1.0108x over previous
#include <cuda_runtime.h>
#include <cuda_fp16.h>
#include <math.h>
#include <stdint.h>

#define BSZ   8
#define HD    128
#define LSEQ  8192
#define PD    256
#define NC2   16
#define CL    (LSEQ / NC2)   // 512
#define SENT  0x7FC00001u

#define NB1   1024           // K1 role CTAs: 128 l-tiles x 8 b
#define NB2   4096           // K2 role CTAs: 32 pg x 8 b x 16 c
#define NB3   1024           // K3 role CTAs

// ---------------- scratch ----------------
__device__ __align__(16) __half g_brh[(size_t)BSZ * PD * LSEQ];
__device__ __align__(16) __half g_bih[(size_t)BSZ * PD * LSEQ];
__device__ __align__(16) __half g_xr[(size_t)BSZ * PD * LSEQ];
__device__ __align__(16) __half g_xi[(size_t)BSZ * PD * LSEQ];
__device__ __align__(8) unsigned long long g_S[BSZ * NC2 * PD];
__device__ int g_c1[BSZ * NC2];   // K1 -> K2 (target 8)
__device__ int g_c2[BSZ * NC2];   // K2 -> K3 (target 32)
__device__ __align__(16) uint4 g_WbPk[32 * 8 * 32];
__device__ __align__(16) uint4 g_WcPk[8 * 40 * 32];

__device__ __forceinline__ float2 cmul(float2 a, float2 b) {
    return make_float2(a.x * b.x - a.y * b.y, a.x * b.y + a.y * b.x);
}
__device__ __forceinline__ unsigned pack_f16(float a, float b) {
    __half2 h = __floats2half2_rn(a, b);
    return *(unsigned*)&h;
}
__device__ __forceinline__ void mma_f16(float c[4], const unsigned a[4], unsigned b0, unsigned b1) {
    asm volatile(
        "mma.sync.aligned.m16n8k16.row.col.f32.f16.f16.f32 "
        "{%0,%1,%2,%3}, {%4,%5,%6,%7}, {%8,%9}, {%0,%1,%2,%3};"
        : "+f"(c[0]), "+f"(c[1]), "+f"(c[2]), "+f"(c[3])
        : "r"(a[0]), "r"(a[1]), "r"(a[2]), "r"(a[3]), "r"(b0), "r"(b1));
}
__device__ __forceinline__ void ldsm_x4_t(unsigned r[4], unsigned addr) {
    asm volatile("ldmatrix.sync.aligned.m8n8.x4.trans.shared.b16 {%0,%1,%2,%3}, [%4];"
                 : "=r"(r[0]), "=r"(r[1]), "=r"(r[2]), "=r"(r[3]) : "r"(addr));
}
__device__ __forceinline__ unsigned smem_u32(const void* p) {
    unsigned a;
    asm("{ .reg .u64 t; cvta.to.shared.u64 t, %1; cvt.u32.u64 %0, t; }" : "=r"(a) : "l"(p));
    return a;
}
__device__ __forceinline__ int ld_acq(const int* p) {
    int v;
    asm volatile("ld.acquire.gpu.global.b32 %0, [%1];" : "=r"(v) : "l"(p) : "memory");
    return v;
}

// ---------------------------------------------------------------------------
// K0: pack weights + reset sentinels/counters.
// ---------------------------------------------------------------------------
__device__ __forceinline__ float wb_get(int r, int c, const float* Bre, const float* Bim) {
    return (r < 256) ? Bre[r * 128 + c] : Bim[(r - 256) * 128 + c];
}
__device__ __forceinline__ float wc_get(int o, int k, const float* Cre, const float* Cim,
                                        const float* Dm) {
    if (k < 256) return Cre[o * 256 + k];
    if (k < 512) return -Cim[o * 256 + (k - 256)];
    return Dm[o * 128 + (k - 512)];
}
__global__ void __launch_bounds__(256) k0_prep(
    const float* __restrict__ Bre, const float* __restrict__ Bim,
    const float* __restrict__ Cre, const float* __restrict__ Cim,
    const float* __restrict__ Dm)
{
    int idx = blockIdx.x * 256 + threadIdx.x;
    for (int j = idx; j < BSZ * NC2 * PD; j += gridDim.x * 256)
        g_S[j] = (unsigned long long)SENT;
    if (idx < BSZ * NC2) { g_c1[idx] = 0; g_c2[idx] = 0; }
    if (idx < 32 * 8 * 32) {
        int lane = idx & 31, ks = (idx >> 5) & 7, blk = idx >> 8;
        int r = blk * 16 + (lane >> 2);
        int cb = ks * 16 + (lane & 3) * 2;
        uint4 o;
        o.x = pack_f16(wb_get(r,     cb,     Bre, Bim), wb_get(r,     cb + 1, Bre, Bim));
        o.y = pack_f16(wb_get(r + 8, cb,     Bre, Bim), wb_get(r + 8, cb + 1, Bre, Bim));
        o.z = pack_f16(wb_get(r,     cb + 8, Bre, Bim), wb_get(r,     cb + 9, Bre, Bim));
        o.w = pack_f16(wb_get(r + 8, cb + 8, Bre, Bim), wb_get(r + 8, cb + 9, Bre, Bim));
        g_WbPk[idx] = o;
    }
    if (idx < 8 * 40 * 32) {
        int lane = idx & 31, t = idx >> 5;
        int ks = t % 40, blk = t / 40;
        int r = blk * 16 + (lane >> 2);
        int cb = ks * 16 + (lane & 3) * 2;
        uint4 o;
        o.x = pack_f16(wc_get(r,     cb,     Cre, Cim, Dm), wc_get(r,     cb + 1, Cre, Cim, Dm));
        o.y = pack_f16(wc_get(r + 8, cb,     Cre, Cim, Dm), wc_get(r + 8, cb + 1, Cre, Cim, Dm));
        o.z = pack_f16(wc_get(r,     cb + 8, Cre, Cim, Dm), wc_get(r,     cb + 9, Cre, Cim, Dm));
        o.w = pack_f16(wc_get(r + 8, cb + 8, Cre, Cim, Dm), wc_get(r + 8, cb + 9, Cre, Cim, Dm));
        g_WcPk[idx] = o;
    }
}

// ---------------------------------------------------------------------------
// shared mma helper
// ---------------------------------------------------------------------------
template<int NKS, int NGS, int SR>
__device__ __forceinline__ void mma_block(float (*c)[4], const uint4* wpk, int ks_stride,
                                          int blk0, int blk1, int ksg0,
                                          unsigned s_base, int lane, int nwbase)
{
    const int brow = (lane & 7) + (lane & 8);
    const int bcol = ((lane >> 4) << 3);
#pragma unroll
    for (int ks = 0; ks < NKS; ks++) {
        const int km = ks * 16;
        const int ksg = ksg0 + ks;
        uint4 ah0 = wpk[(blk0 * ks_stride + ksg) * 32 + lane];
        uint4 ah1 = wpk[(blk1 * ks_stride + ksg) * 32 + lane];
#pragma unroll
        for (int ng = 0; ng < NGS; ng++) {
            int n0 = nwbase + ng * 16;
            unsigned off = (unsigned)(((km + brow) * SR + n0 + bcol) * 2);
            unsigned bb[4];
            ldsm_x4_t(bb, s_base + off);
            mma_f16(c[0 * 2 * NGS + ng * 2 + 0], (const unsigned*)&ah0, bb[0], bb[1]);
            mma_f16(c[0 * 2 * NGS + ng * 2 + 1], (const unsigned*)&ah0, bb[2], bb[3]);
            mma_f16(c[1 * 2 * NGS + ng * 2 + 0], (const unsigned*)&ah1, bb[0], bb[1]);
            mma_f16(c[1 * 2 * NGS + ng * 2 + 1], (const unsigned*)&ah1, bb[2], bb[3]);
        }
    }
}

#define SRR 72

// ---------------------------------------------------------------------------
// role bodies
// ---------------------------------------------------------------------------
__device__ void k1_role(int r, const float* __restrict__ u, __half* s_raw)
{
    __half (*sh)[SRR] = (__half(*)[SRR])s_raw;
    const int lt = r & 127, b = r >> 7;
    const int lbase = lt * 64;
    const int tid = threadIdx.x, lane = tid & 31, wid = tid >> 5;
    const int wm = wid >> 1, wn = wid & 1;
    const unsigned s_base = smem_u32(&sh[0][0]);

    {
        const int row = tid >> 1, half = tid & 1;
        const float* s = u + ((size_t)b * HD + row) * LSEQ + lbase + half * 32;
#pragma unroll
        for (int q = 0; q < 4; q++) {
            float4 v0 = *(const float4*)(s + q * 8);
            float4 v1 = *(const float4*)(s + q * 8 + 4);
            uint4 pk;
            pk.x = pack_f16(v0.x, v0.y); pk.y = pack_f16(v0.z, v0.w);
            pk.z = pack_f16(v1.x, v1.y); pk.w = pack_f16(v1.z, v1.w);
            *(uint4*)&sh[row][half * 32 + q * 8] = pk;
        }
    }
    __syncthreads();

#pragma unroll 1
    for (int mt = 0; mt < 4; mt++) {
        float c[8][4];
#pragma unroll
        for (int i = 0; i < 8; i++)
#pragma unroll
            for (int q = 0; q < 4; q++) c[i][q] = 0.f;

        const int blk0 = mt * 8 + wm * 2;
        mma_block<8, 2, SRR>(c, g_WbPk, 8, blk0, blk0 + 1, 0, s_base, lane, wn * 32);

#pragma unroll
        for (int mi = 0; mi < 2; mi++) {
#pragma unroll
            for (int ni = 0; ni < 4; ni++) {
                const float* cc = c[mi * 4 + ni];
                int r0  = mt * 128 + wm * 32 + mi * 16 + (lane >> 2);
                int col = lbase + wn * 32 + ni * 8 + (lane & 3) * 2;
                {
                    __half* plane = (r0 < 256) ? g_brh : g_bih;
                    int pr = (r0 < 256) ? r0 : r0 - 256;
                    *(__half2*)&plane[((size_t)b * PD + pr) * LSEQ + col] =
                        __floats2half2_rn(cc[0], cc[1]);
                }
                int r1 = r0 + 8;
                {
                    __half* plane = (r1 < 256) ? g_brh : g_bih;
                    int pr = (r1 < 256) ? r1 : r1 - 256;
                    *(__half2*)&plane[((size_t)b * PD + pr) * LSEQ + col] =
                        __floats2half2_rn(cc[2], cc[3]);
                }
            }
        }
    }

    // publish: Bu tile done
    __threadfence();
    __syncthreads();
    if (tid == 0) atomicAdd(&g_c1[b * NC2 + (lt >> 3)], 1);
}

__device__ void k2_role(int j, const float* __restrict__ Are, const float* __restrict__ Aim)
{
    const int pg = j & 31, b = (j >> 5) & 7, c = j >> 8;
    const int tid = threadIdx.x, wid = tid >> 5, lane = tid & 31;
    const int p = pg * 8 + wid;

    // wait for Bu chunk (b,c)
    if (tid == 0) {
        while (ld_acq(&g_c1[b * NC2 + c]) < 8) __nanosleep(64);
    }
    __syncthreads();

    const float2 a = make_float2(Are[p], Aim[p]);
    float2 g = a;
#pragma unroll
    for (int k = 0; k < 4; k++) g = cmul(g, g);         // a^16
    float2 gt = make_float2(1.f, 0.f), t2 = g;
#pragma unroll
    for (int bit = 1; bit < 32; bit <<= 1) {
        if (lane & bit) gt = cmul(gt, t2);
        t2 = cmul(t2, t2);
    }
    const float2 a512 = t2;

    const size_t base = ((size_t)b * PD + p) * LSEQ + (size_t)c * CL + lane * 16;

    __half2 hr[8], hi[8];
    *(uint4*)&hr[0] = *(const uint4*)(g_brh + base);
    *(uint4*)&hr[4] = *(const uint4*)(g_brh + base + 8);
    *(uint4*)&hi[0] = *(const uint4*)(g_bih + base);
    *(uint4*)&hi[4] = *(const uint4*)(g_bih + base + 8);

    float2 X[16];
    float2 x = make_float2(0.f, 0.f);
#pragma unroll
    for (int jj = 0; jj < 16; jj++) {
        float2 rr = __half22float2(hr[jj >> 1]);
        float2 ii = __half22float2(hi[jj >> 1]);
        float br = (jj & 1) ? rr.y : rr.x;
        float bi = (jj & 1) ? ii.y : ii.x;
        float2 s = make_float2(x.x + br, x.y + bi);
        x = cmul(a, s);
        X[jj] = x;
    }

    float2 v = x;
    float2 gd = g;
#pragma unroll
    for (int d = 1; d < 32; d <<= 1) {
        float ox = __shfl_up_sync(0xffffffffu, v.x, d);
        float oy = __shfl_up_sync(0xffffffffu, v.y, d);
        if (lane >= d) {
            v.x += gd.x * ox - gd.y * oy;
            v.y += gd.x * oy + gd.y * ox;
        }
        gd = cmul(gd, gd);
    }
    float cux = __shfl_up_sync(0xffffffffu, v.x, 1);
    float cuy = __shfl_up_sync(0xffffffffu, v.y, 1);
    float2 Cth = (lane == 0) ? make_float2(0.f, 0.f) : make_float2(cux, cuy);
    float2 Eloc = make_float2(__shfl_sync(0xffffffffu, v.x, 31),
                              __shfl_sync(0xffffffffu, v.y, 31));

    const int sidx = (b * NC2 + c) * PD + p;
    float2 C0 = make_float2(0.f, 0.f);
    if (lane == 0) {
        if (c > 0) {
            unsigned long long w;
            while (true) {
                asm volatile("ld.acquire.gpu.global.b64 %0, [%1];"
                             : "=l"(w) : "l"(g_S + sidx - PD) : "memory");
                if ((unsigned)w != SENT) break;
                __nanosleep(64);
            }
            C0.x = __uint_as_float((unsigned)w);
            C0.y = __uint_as_float((unsigned)(w >> 32));
        }
        float2 Et = make_float2(Eloc.x + a512.x * C0.x - a512.y * C0.y,
                                Eloc.y + a512.x * C0.y + a512.y * C0.x);
        unsigned long long pub = (unsigned long long)__float_as_uint(Et.x)
                               | ((unsigned long long)__float_as_uint(Et.y) << 32);
        asm volatile("st.release.gpu.global.b64 [%0], %1;"
                     :: "l"(g_S + sidx), "l"(pub) : "memory");
    }
    C0.x = __shfl_sync(0xffffffffu, C0.x, 0);
    C0.y = __shfl_sync(0xffffffffu, C0.y, 0);

    float2 Ct = make_float2(Cth.x + gt.x * C0.x - gt.y * C0.y,
                            Cth.y + gt.x * C0.y + gt.y * C0.x);
    float2 ck = cmul(a, Ct);
#pragma unroll
    for (int jj = 0; jj < 16; jj++) {
        X[jj].x += ck.x; X[jj].y += ck.y;
        if (jj < 15) ck = cmul(ck, a);
    }

    __half2 orr[8], ori[8];
#pragma unroll
    for (int jj = 0; jj < 8; jj++) {
        orr[jj] = __floats2half2_rn(X[2 * jj].x, X[2 * jj + 1].x);
        ori[jj] = __floats2half2_rn(X[2 * jj].y, X[2 * jj + 1].y);
    }
    *(uint4*)(g_xr + base)     = *(uint4*)&orr[0];
    *(uint4*)(g_xr + base + 8) = *(uint4*)&orr[4];
    *(uint4*)(g_xi + base)     = *(uint4*)&ori[0];
    *(uint4*)(g_xi + base + 8) = *(uint4*)&ori[4];

    // publish: x chunk contribution done
    __threadfence();
    __syncthreads();
    if (tid == 0) atomicAdd(&g_c2[b * NC2 + c], 1);
}

__device__ void k3_role(int k, const float* __restrict__ u, float* __restrict__ out,
                        __half* s_raw)
{
    __half (*sh)[64][SRR] = (__half(*)[64][SRR])s_raw;
    const int lt = k & 127, b = k >> 7;
    const int lbase = lt * 64;
    const int tid = threadIdx.x, lane = tid & 31, wid = tid >> 5;
    const int wm = wid >> 1, wn = wid & 1;
    const unsigned s_base0 = smem_u32(&sh[0][0][0]);
    const unsigned s_base1 = smem_u32(&sh[1][0][0]);
    const int row = tid >> 2, quarter = tid & 3;

    // wait for x chunk (b, lt>>3)
    if (tid == 0) {
        while (ld_acq(&g_c2[b * NC2 + (lt >> 3)]) < 32) __nanosleep(64);
    }
    __syncthreads();

    float c[8][4];
#pragma unroll
    for (int i = 0; i < 8; i++)
#pragma unroll
        for (int q = 0; q < 4; q++) c[i][q] = 0.f;

    uint4 pv[4];

    auto prefetch = [&](int cc) {
        if (cc < 8) {
            const __half* src = (cc >= 4) ? g_xi : g_xr;
            const uint4* s = (const uint4*)(src +
                ((size_t)b * PD + (cc & 3) * 64 + row) * LSEQ + lbase + quarter * 16);
#pragma unroll
            for (int q = 0; q < 2; q++) pv[q] = s[q];
        } else {
            const uint4* s = (const uint4*)(u +
                ((size_t)b * HD + (cc - 8) * 64 + row) * LSEQ + lbase + quarter * 16);
#pragma unroll
            for (int q = 0; q < 4; q++) pv[q] = s[q];
        }
    };
    auto stage_store = [&](int cc, int buf) {
        if (cc < 8) {
#pragma unroll
            for (int q = 0; q < 2; q++)
                *(uint4*)&sh[buf][row][quarter * 16 + q * 8] = pv[q];
        } else {
#pragma unroll
            for (int q = 0; q < 2; q++) {
                float4 v0 = *(float4*)&pv[2 * q];
                float4 v1 = *(float4*)&pv[2 * q + 1];
                uint4 pk;
                pk.x = pack_f16(v0.x, v0.y); pk.y = pack_f16(v0.z, v0.w);
                pk.z = pack_f16(v1.x, v1.y); pk.w = pack_f16(v1.z, v1.w);
                *(uint4*)&sh[buf][row][quarter * 16 + q * 8] = pk;
            }
        }
    };

    prefetch(0);
    stage_store(0, 0);
    __syncthreads();

    const int blk0 = wm * 2;
#pragma unroll 1
    for (int cc = 0; cc < 10; cc++) {
        if (cc < 9) prefetch(cc + 1);
        mma_block<4, 2, SRR>(c, g_WcPk, 40, blk0, blk0 + 1, cc * 4,
                             (cc & 1) ? s_base1 : s_base0, lane, wn * 32);
        if (cc < 9) stage_store(cc + 1, (cc + 1) & 1);
        __syncthreads();
    }

#pragma unroll
    for (int mi = 0; mi < 2; mi++) {
#pragma unroll
        for (int ni = 0; ni < 4; ni++) {
            const float* cc = c[mi * 4 + ni];
            int r0  = wm * 32 + mi * 16 + (lane >> 2);
            int col = lbase + wn * 32 + ni * 8 + (lane & 3) * 2;
            float y0 = cc[0], y1 = cc[1], y2 = cc[2], y3 = cc[3];
            y0 = 0.5f * y0 * (1.f + erff(y0 * 0.70710678118654752f));
            y1 = 0.5f * y1 * (1.f + erff(y1 * 0.70710678118654752f));
            y2 = 0.5f * y2 * (1.f + erff(y2 * 0.70710678118654752f));
            y3 = 0.5f * y3 * (1.f + erff(y3 * 0.70710678118654752f));
            *(float2*)&out[((size_t)b * HD + r0) * LSEQ + col]     = make_float2(y0, y1);
            *(float2*)&out[((size_t)b * HD + r0 + 8) * LSEQ + col] = make_float2(y2, y3);
        }
    }
}

// ---------------------------------------------------------------------------
// Mega-kernel: roles by blockIdx (K1 | K2 | K3). Producers < consumers.
// ---------------------------------------------------------------------------
__global__ void __launch_bounds__(256, 3) mega(
    const float* __restrict__ u,
    const float* __restrict__ Are, const float* __restrict__ Aim,
    float* __restrict__ out)
{
    __shared__ __align__(16) __half s_raw[2 * 64 * SRR];   // 18432 B, shared by K1/K3
    const int bi = blockIdx.x;
    if (bi < NB1) {
        k1_role(bi, u, s_raw);
    } else if (bi < NB1 + NB2) {
        k2_role(bi - NB1, Are, Aim);
    } else {
        k3_role(bi - NB1 - NB2, u, out, s_raw);
    }
}

// ---------------------------------------------------------------------------
extern "C" void kernel_launch(void* const* d_in, const int* in_sizes, int n_in,
                              void* d_out, int out_size)
{
    (void)in_sizes; (void)n_in; (void)out_size;
    const float* u   = (const float*)d_in[0];
    const float* Are = (const float*)d_in[1];
    const float* Aim = (const float*)d_in[2];
    const float* Bre = (const float*)d_in[3];
    const float* Bim = (const float*)d_in[4];
    const float* Cre = (const float*)d_in[5];
    const float* Cim = (const float*)d_in[6];
    const float* Dm  = (const float*)d_in[7];
    float* out = (float*)d_out;

    k0_prep <<<80, 256>>>(Bre, Bim, Cre, Cim, Dm);
    mega    <<<NB1 + NB2 + NB3, 256>>>(u, Are, Aim, out);
}